// round 14
// baseline (speedup 1.0000x reference)
#include <cuda_runtime.h>
#include <cuda_fp16.h>
#include <mma.h>

using namespace nvcuda;

#define N_NODES 50000
#define N_EDGES 800000
#define IN_DIM  128
#define H_HEADS 4
#define F_DIM   32
#define HF      128      // H*F
#define OUT_ROW 160      // (H+1)*F
#define NEG_SLOPE 0.2f

// ---------------- device scratch (no allocs allowed) ----------------
// g_src_pack[node*32 + lane] = uint4: halves 0-3 = el_mut[lane*4..], halves 4-7 = el_self[lane*4..]
__device__ uint4  g_src_pack [N_NODES * 32];
__device__ __half g_er_mut   [N_NODES * HF];
__device__ float  g_denom    [N_NODES * H_HEADS];
__device__ int    g_idx64;

// ---------------- helpers ----------------
__device__ __forceinline__ long load_index(const void* p, int e, int is64) {
    return is64 ? (long)((const long long*)p)[e] : (long)((const int*)p)[e];
}

// Zero ft region of output (cols 32..159 per node) and denom; detect index width.
__global__ void zero_kernel(float4* __restrict__ out, const int* __restrict__ src) {
    long i = (long)blockIdx.x * blockDim.x + threadIdx.x;
    if (i == 0) {
        int all0 = 1;
        #pragma unroll
        for (int k = 1; k < 16; k += 2) all0 &= (src[k] == 0);
        g_idx64 = all0;
    }
    if (i < (long)N_NODES * 32) {
        int n = (int)(i >> 5);
        int j = (int)(i & 31);
        out[(long)n * 40 + 8 + j] = make_float4(0.f, 0.f, 0.f, 0.f);
    }
    if (i < (N_NODES * H_HEADS) / 4) {
        ((float4*)g_denom)[i] = make_float4(0.f, 0.f, 0.f, 0.f);
    }
}

// ---------------- projAll: all 4 projections, A staged ONCE ----------------
// Block = 128 M-rows; 8 warps, warp tile 16 M x ncols.
// Loop ytile over {Wsrc, Wdst, Wself, Wlin}: restage only B per ytile.
// Epilogue staging aliases the B buffer (dead after its mma); A persists.
#define SA_STRIDE 136
#define SA_BYTES  (128 * SA_STRIDE * 2)     // 34816

__global__ __launch_bounds__(256, 2)
void projAll_kernel(const float* __restrict__ feat,
                    const float* __restrict__ Wsrc, const float* __restrict__ bsrc,
                    const float* __restrict__ Wdst, const float* __restrict__ bdst,
                    const float* __restrict__ Wself, const float* __restrict__ bself,
                    const float* __restrict__ Wlin, const float* __restrict__ blin,
                    float* __restrict__ out)
{
    __shared__ __align__(16) unsigned char sraw[2 * SA_BYTES];   // 69632 B
    __half* As  = (__half*)sraw;
    __half* Bs  = (__half*)(sraw + SA_BYTES);
    float*  Cst = (float*)(sraw + SA_BYTES);   // aliases Bs (time-disjoint)

    int t    = threadIdx.x;
    int wid  = t >> 5;
    int lane = t & 31;
    int rowBase = blockIdx.x * 128;

    // ---- stage A once (feat tile, fp32 -> half) ----
    #pragma unroll
    for (int i = 0; i < 8; i++) {
        int idx = t + i * 256;            // 0..2047 slots, each = 8 cols
        int r   = idx >> 4;
        int c8  = idx & 15;
        int grow = rowBase + r;
        float4 v0 = make_float4(0.f, 0.f, 0.f, 0.f);
        float4 v1 = make_float4(0.f, 0.f, 0.f, 0.f);
        if (grow < N_NODES) {
            v0 = ((const float4*)feat)[(long)grow * 32 + c8 * 2];
            v1 = ((const float4*)feat)[(long)grow * 32 + c8 * 2 + 1];
        }
        uint4 u;
        *((__half2*)&u.x) = __floats2half2_rn(v0.x, v0.y);
        *((__half2*)&u.y) = __floats2half2_rn(v0.z, v0.w);
        *((__half2*)&u.z) = __floats2half2_rn(v1.x, v1.y);
        *((__half2*)&u.w) = __floats2half2_rn(v1.z, v1.w);
        *((uint4*)&As[r * SA_STRIDE + c8 * 8]) = u;
    }

    const float* Wt[4] = {Wsrc, Wdst, Wself, Wlin};
    const float* bt[4] = {bsrc, bdst, bself, blin};

    int r2 = lane >> 1;                   // 0..15 (epilogue row)
    int hc = lane & 1;                    // epilogue col-half (8 cols)
    int grow = rowBase + wid * 16 + r2;

    for (int yt = 0; yt < 4; yt++) {
        __syncthreads();   // A ready / previous epilogue done with Bs
        const float* W = Wt[yt];

        // ---- stage B (fp32 -> half) ----
        if (yt < 3) {
            #pragma unroll
            for (int i = 0; i < 8; i++) {
                int idx = t + i * 256;    // 0..2047: 128 rows x 16 col8-groups
                int r   = idx >> 4;
                int c8  = idx & 15;
                float4 w0 = ((const float4*)W)[idx * 2];
                float4 w1 = ((const float4*)W)[idx * 2 + 1];
                uint4 uw;
                *((__half2*)&uw.x) = __floats2half2_rn(w0.x, w0.y);
                *((__half2*)&uw.y) = __floats2half2_rn(w0.z, w0.w);
                *((__half2*)&uw.z) = __floats2half2_rn(w1.x, w1.y);
                *((__half2*)&uw.w) = __floats2half2_rn(w1.z, w1.w);
                *((uint4*)&Bs[r * SA_STRIDE + c8 * 8]) = uw;
            }
        } else {
            // W_lin: 128 rows x 32 cols = 512 col8-slots; 256 threads x 2 iters
            #pragma unroll
            for (int i = 0; i < 2; i++) {
                int idx = t + i * 256;    // 0..511
                int r   = idx >> 2;       // 0..127 (full 128 k-rows)
                int c8  = idx & 3;        // 4 groups of 8 cols
                float4 w0 = ((const float4*)W)[r * 8 + c8 * 2];
                float4 w1 = ((const float4*)W)[r * 8 + c8 * 2 + 1];
                uint4 uw;
                *((__half2*)&uw.x) = __floats2half2_rn(w0.x, w0.y);
                *((__half2*)&uw.y) = __floats2half2_rn(w0.z, w0.w);
                *((__half2*)&uw.z) = __floats2half2_rn(w1.x, w1.y);
                *((__half2*)&uw.w) = __floats2half2_rn(w1.z, w1.w);
                *((uint4*)&Bs[r * SA_STRIDE + c8 * 8]) = uw;
            }
        }
        __syncthreads();

        int nf = (yt == 3) ? 2 : 8;

        wmma::fragment<wmma::accumulator, 16, 16, 16, float> acc[8];
        #pragma unroll
        for (int n = 0; n < 8; n++)
            if (n < nf) wmma::fill_fragment(acc[n], 0.f);

        #pragma unroll
        for (int k0 = 0; k0 < IN_DIM; k0 += 16) {
            wmma::fragment<wmma::matrix_a, 16, 16, 16, __half, wmma::row_major> a;
            wmma::load_matrix_sync(a, As + wid * 16 * SA_STRIDE + k0, SA_STRIDE);
            #pragma unroll
            for (int n = 0; n < 8; n++) {
                if (n < nf) {
                    wmma::fragment<wmma::matrix_b, 16, 16, 16, __half, wmma::row_major> b;
                    wmma::load_matrix_sync(b, Bs + k0 * SA_STRIDE + n * 16, SA_STRIDE);
                    wmma::mma_sync(acc[n], a, b, acc[n]);
                }
            }
        }
        __syncthreads();   // all warps done reading Bs -> reuse as Cst

        // ---- epilogue: per-frag smem restage, bias, convert, store ----
        float* cw = Cst + wid * 320;      // 16 x 20 floats per warp
        const float* bias = bt[yt];

        #pragma unroll
        for (int n = 0; n < 8; n++) {
            if (n >= nf) break;
            wmma::store_matrix_sync(cw, acc[n], 20, wmma::mem_row_major);
            __syncwarp();
            if (grow < N_NODES) {
                int ncol = n * 16 + hc * 8;
                float f[8];
                #pragma unroll
                for (int j = 0; j < 8; j++)
                    f[j] = cw[r2 * 20 + hc * 8 + j] + bias[ncol + j];
                uint2 ua, ub;
                *((__half2*)&ua.x) = __floats2half2_rn(f[0], f[1]);
                *((__half2*)&ua.y) = __floats2half2_rn(f[2], f[3]);
                *((__half2*)&ub.x) = __floats2half2_rn(f[4], f[5]);
                *((__half2*)&ub.y) = __floats2half2_rn(f[6], f[7]);
                int slot = ncol >> 2;     // lane index (4 features per slot)
                if (yt == 0) {
                    // el_mut -> pack halves 0-3 (uint4 .x,.y)
                    uint2* p0 = (uint2*)&g_src_pack[(long)grow * 32 + slot];
                    uint2* p1 = (uint2*)&g_src_pack[(long)grow * 32 + slot + 1];
                    *p0 = ua;
                    *p1 = ub;
                } else if (yt == 1) {
                    uint4 u; u.x = ua.x; u.y = ua.y; u.z = ub.x; u.w = ub.y;
                    *((uint4*)&g_er_mut[(long)grow * HF + ncol]) = u;
                } else if (yt == 2) {
                    // el_self -> pack halves 4-7 (uint4 .z,.w)
                    uint2* p0 = (uint2*)((char*)&g_src_pack[(long)grow * 32 + slot] + 8);
                    uint2* p1 = (uint2*)((char*)&g_src_pack[(long)grow * 32 + slot + 1] + 8);
                    *p0 = ua;
                    *p1 = ub;
                } else {
                    // feat_lin -> out[:, 0, 0:32] (row stride 40 float4)
                    float4* o4 = (float4*)out + (long)grow * 40 + (ncol >> 2);
                    o4[0] = make_float4(f[0], f[1], f[2], f[3]);
                    o4[1] = make_float4(f[4], f[5], f[6], f[7]);
                }
            }
            __syncwarp();
        }
    }
}

// ---------------- fused edge pass: score + unnormalized aggregate ----------
// FOUR edges per warp; lane l covers features 4l..4l+3, head = l>>3.
// src side is ONE LDG.128 (el_mut + el_self packed); dst side one LDG.64.
// After the xor-reduce every lane holds the full head score: each lane
// computes e = exp(p), REDs e*el_self (unnormalized) into out's ft region,
// the group leader REDs e into denom; finalize divides later.
__global__ __launch_bounds__(256, 6)
void edge_fused_kernel(const void* __restrict__ srcp, const void* __restrict__ dstp,
                       const float* __restrict__ attn, float* __restrict__ out)
{
    int warp = (blockIdx.x * blockDim.x + threadIdx.x) >> 5;
    int lane = threadIdx.x & 31;
    int e0 = warp * 4;
    if (e0 >= N_EDGES) return;
    int is64 = g_idx64;

    int s[4], d[4];
    #pragma unroll
    for (int i = 0; i < 4; i++) {
        s[i] = (int)load_index(srcp, e0 + i, is64);
        d[i] = (int)load_index(dstp, e0 + i, is64);
    }

    float4 atf = ((const float4*)attn)[lane];
    __half2 a0 = __floats2half2_rn(atf.x, atf.y);
    __half2 a1 = __floats2half2_rn(atf.z, atf.w);
    const __half2 slope = __floats2half2_rn(NEG_SLOPE, NEG_SLOPE);

    // 8 independent gathers in flight (4x LDG.128 src-pack + 4x LDG.64 er)
    uint4 pl[4];
    uint2 ur[4];
    #pragma unroll
    for (int i = 0; i < 4; i++) {
        pl[i] = g_src_pack[(long)s[i] * 32 + lane];
        ur[i] = ((const uint2*)g_er_mut)[(long)d[i] * 32 + lane];
    }

    int h = lane >> 3;
    bool leader = (lane & 7) == 0;

    #pragma unroll
    for (int i = 0; i < 4; i++) {
        __half2 x0 = __hadd2(*((__half2*)&pl[i].x), *((__half2*)&ur[i].x));
        __half2 x1 = __hadd2(*((__half2*)&pl[i].y), *((__half2*)&ur[i].y));
        x0 = __hmax2(x0, __hmul2(x0, slope));          // leaky = max(x, 0.2x)
        x1 = __hmax2(x1, __hmul2(x1, slope));
        __half2 p2 = __hfma2(x1, a1, __hmul2(x0, a0));
        float2 pf = __half22float2(p2);
        float p = pf.x + pf.y;

        // xor-reduce: full head score ends up in EVERY lane of the group
        p += __shfl_xor_sync(0xFFFFFFFFu, p, 4);
        p += __shfl_xor_sync(0xFFFFFFFFu, p, 2);
        p += __shfl_xor_sync(0xFFFFFFFFu, p, 1);

        // softmax-invariant: segment_max skipped (scores O(1))
        float e = __expf(p);

        if (leader) {
            float* dp = &g_denom[d[i] * 4 + h];
            asm volatile("red.global.add.f32 [%0], %1;"
                         :: "l"(dp), "f"(e) : "memory");
        }

        float2 f0 = __half22float2(*((__half2*)&pl[i].z));
        float2 f1 = __half22float2(*((__half2*)&pl[i].w));
        float4 m = make_float4(f0.x * e, f0.y * e, f1.x * e, f1.y * e);
        float* p4 = out + (long)d[i] * OUT_ROW + 32 + lane * 4;
        asm volatile("red.global.add.v4.f32 [%0], {%1,%2,%3,%4};"
                     :: "l"(p4), "f"(m.x), "f"(m.y), "f"(m.z), "f"(m.w) : "memory");
    }
}

// ---------------- finalize: divide ft by denom (deg-0 -> 0) ----------------
// 2 lanes (8 cols, same head) per thread.
__global__ __launch_bounds__(256)
void finalize_kernel(float* __restrict__ out)
{
    int i = blockIdx.x * blockDim.x + threadIdx.x;   // node*16 + pair
    if (i >= N_NODES * 16) return;
    int n = i >> 4;
    int j = i & 15;                 // pair of lanes 2j, 2j+1 (same head)
    float den = g_denom[n * 4 + (j >> 2)];
    float inv = (den > 0.f) ? 1.f / den : 0.f;
    float4* p = (float4*)(out + (long)n * OUT_ROW + 32) + 2 * j;
    float4 v0 = p[0];
    float4 v1 = p[1];
    v0.x *= inv; v0.y *= inv; v0.z *= inv; v0.w *= inv;
    v1.x *= inv; v1.y *= inv; v1.z *= inv; v1.w *= inv;
    p[0] = v0;
    p[1] = v1;
}

// ---------------- stream fork resources (host-side, static init) ----------------
struct ForkResources {
    cudaStream_t s2;
    cudaEvent_t  e0, eZ;
    bool ok;
    ForkResources() : ok(false) {
        if (cudaStreamCreateWithFlags(&s2, cudaStreamNonBlocking) != cudaSuccess) return;
        if (cudaEventCreateWithFlags(&e0, cudaEventDisableTiming) != cudaSuccess) return;
        if (cudaEventCreateWithFlags(&eZ, cudaEventDisableTiming) != cudaSuccess) return;
        ok = true;
    }
};
static ForkResources g_fork;

// ---------------- launch ----------------
extern "C" void kernel_launch(void* const* d_in, const int* in_sizes, int n_in,
                              void* d_out, int out_size)
{
    const float* feat  = (const float*)d_in[0];
    const float* Wsrc  = (const float*)d_in[1];
    const float* bsrc  = (const float*)d_in[2];
    const float* Wdst  = (const float*)d_in[3];
    const float* bdst  = (const float*)d_in[4];
    const float* Wself = (const float*)d_in[5];
    const float* bself = (const float*)d_in[6];
    const float* Wlin  = (const float*)d_in[7];
    const float* blin  = (const float*)d_in[8];
    const float* attn  = (const float*)d_in[9];
    const void*  src   = d_in[10];
    const void*  dst   = d_in[11];
    float* out = (float*)d_out;

    int projBlocks = (N_NODES + 127) / 128;       // 391, each does all 4 GEMMs
    int edgeBlocks = (N_EDGES / 4 + 7) / 8;       // 4 edges/warp
    int finBlocks  = (N_NODES * 16 + 255) / 256;

    if (g_fork.ok) {
        // legal fork: s2 joins capture via event wait BEFORE receiving work
        cudaEventRecord(g_fork.e0, 0);
        cudaStreamWaitEvent(g_fork.s2, g_fork.e0, 0);

        // s2: zero + detect only (overlaps projAll)
        zero_kernel<<<(N_NODES * 32 + 255) / 256, 256, 0, g_fork.s2>>>(
            (float4*)out, (const int*)src);
        cudaEventRecord(g_fork.eZ, g_fork.s2);

        // main: all projections -> fused edge pass -> finalize
        projAll_kernel<<<projBlocks, 256>>>(feat, Wsrc, bsrc, Wdst, bdst,
                                            Wself, bself, Wlin, blin, out);
        cudaStreamWaitEvent(0, g_fork.eZ, 0);
        edge_fused_kernel<<<edgeBlocks, 256>>>(src, dst, attn, out);
        finalize_kernel<<<finBlocks, 256>>>(out);
    } else {
        zero_kernel<<<(N_NODES * 32 + 255) / 256, 256>>>((float4*)out, (const int*)src);
        projAll_kernel<<<projBlocks, 256>>>(feat, Wsrc, bsrc, Wdst, bdst,
                                            Wself, bself, Wlin, blin, out);
        edge_fused_kernel<<<edgeBlocks, 256>>>(src, dst, attn, out);
        finalize_kernel<<<finBlocks, 256>>>(out);
    }
}